// round 1
// baseline (speedup 1.0000x reference)
#include <cuda_runtime.h>
#include <math.h>

// ---------------------------------------------------------------------------
// ModalUncertaintyEstimator — B=64, C=8, H=256, M=32
// outputs (f32, concatenated):
//   [0]       modal_energies        512*1024
//   [524288]  modal_uncertainties   512*1024
//   [1048576] energy_fractions      512*1024
//   [1572864] weighted_importance   512*1024
//   [2097152] uncertainty_spectrum  1024
//   [2098176] energy_spectrum       1024
//   [2099200] modal_errors          512*1024
//   [2623488] calibration_scores    1024
// ---------------------------------------------------------------------------

#define NIMG 512          // B*C
#define HH   256
#define MM_  32
#define SZ   (NIMG * 1024)

#define OFF_EN  0
#define OFF_MU  (SZ)
#define OFF_FR  (2 * SZ)
#define OFF_WI  (3 * SZ)
#define OFF_US  (4 * SZ)
#define OFF_ES  (4 * SZ + 1024)
#define OFF_ER  (4 * SZ + 2048)
#define OFF_CAL (5 * SZ + 2048)

typedef unsigned long long u64;

__device__ __forceinline__ u64 pk2(float x, float y) {
    u64 r; asm("mov.b64 %0,{%1,%2};" : "=l"(r) : "f"(x), "f"(y)); return r;
}
__device__ __forceinline__ void unpk2(u64 v, float& x, float& y) {
    asm("mov.b64 {%0,%1},%2;" : "=f"(x), "=f"(y) : "l"(v));
}
__device__ __forceinline__ u64 ffma2(u64 a, u64 b, u64 c) {
    u64 d; asm("fma.rn.f32x2 %0,%1,%2,%3;" : "=l"(d) : "l"(a), "l"(b), "l"(c)); return d;
}

// scratch (device globals: allocation-free)
__device__ u64   g_T1[1024 * 32 * 256];   // 64 MB: per-image T1[k1][y] packed (re,im)
__device__ u64   g_modes[1024 * 1024];    // 8 MB: modes, imgs 0..511 = pred, 512..1023 = gt
__device__ u64   g_tabA[128 * 32];        // twiddle table [x][k] = (cos,sin)(2*pi*k*x/256)
__device__ float g_tote[NIMG];

// ---------------------------------------------------------------------------
__global__ void k_init() {
    int t = threadIdx.x;
    for (int i = t; i < 128 * 32; i += 256) {
        int x = i >> 5, k = i & 31;
        double ang = (2.0 * 3.14159265358979323846 / 256.0) * (double)(k * x);
        double s, c; sincos(ang, &s, &c);
        g_tabA[i] = pk2((float)c, (float)s);
    }
}

// ---------------------------------------------------------------------------
// Stage A: T1[k1,y] = sum_x f[x,y] * exp(-2*pi*i*k1*x/256), k1 in [0,32)
// Folded over x <-> 256-x:
//   re = f0 + (-1)^k f128 + sum_{x=1..127} (f[x]+f[256-x]) cos
//   im = -( sum_{x=1..127} (f[x]-f[256-x]) sin )
// grid: 2048 = 1024 images (pred then gt) x 2 y-chunks of 128 cols
// block: 256 threads = (y in [0,128)) x (kh in {0,1} -> 16 k's each)
__global__ void __launch_bounds__(256, 1) k_dft_x(const float* __restrict__ pred,
                                                  const float* __restrict__ gt) {
    extern __shared__ float smem[];
    float* sf  = smem;                         // [256][128]
    u64*   stw = (u64*)(smem + 256 * 128);     // [128][32]

    int bid = blockIdx.x;
    int img = bid >> 1;
    int ych = (bid & 1) * 128;
    const float* src = (img < NIMG) ? (pred + (size_t)img * 65536)
                                    : (gt + (size_t)(img - NIMG) * 65536);
    int tid = threadIdx.x;

    for (int i = tid; i < 8192; i += 256) {     // 32768 floats as float4
        int x = i >> 5;
        int off = (i & 31) * 4;
        float4 v = *(const float4*)(src + x * 256 + ych + off);
        *(float4*)(sf + x * 128 + off) = v;
    }
    for (int i = tid; i < 4096; i += 256) stw[i] = g_tabA[i];
    __syncthreads();

    int y = tid & 127;
    int kbase = (tid >> 7) * 16;

    float f0 = sf[y];
    float f128 = sf[128 * 128 + y];

    u64 acc[16];
#pragma unroll
    for (int j = 0; j < 16; j++) {
        int k = kbase + j;
        float re0 = f0 + ((k & 1) ? -f128 : f128);
        acc[j] = pk2(re0, 0.f);
    }

    for (int x = 1; x < 128; x++) {
        float fx = sf[x * 128 + y];
        float fr = sf[(256 - x) * 128 + y];
        u64 eo = pk2(fx + fr, fx - fr);
        const u64* tw = stw + x * 32 + kbase;
#pragma unroll
        for (int j = 0; j < 16; j++) acc[j] = ffma2(eo, tw[j], acc[j]);
    }

    size_t base = ((size_t)img * 32) * 256 + ych + y;
#pragma unroll
    for (int j = 0; j < 16; j++) {
        float re, sn; unpk2(acc[j], re, sn);
        g_T1[base + (size_t)(kbase + j) * 256] = pk2(re, -sn);
    }
}

// ---------------------------------------------------------------------------
// Stage B: modes[k1,k2] = sum_y T1[k1,y] * exp(-2*pi*i*k2*y/256)
// Folded over y <-> 256-y: contribution = P*cos - i*Q*sin
//   re += Pr*c + Qi*s ; im += Pi*c - Qr*s
// grid: 1024 images, block 256 = (k1 in [0,32)) x (k2q in [0,8) -> 4 k2 each)
__global__ void __launch_bounds__(256, 2) k_dft_y() {
    extern __shared__ u64 sm2[];
    u64* sT  = sm2;            // [32][256]
    u64* stw = sm2 + 8192;     // [128][32]

    int img = blockIdx.x;
    int tid = threadIdx.x;
    for (int i = tid; i < 8192; i += 256) sT[i] = g_T1[(size_t)img * 8192 + i];
    for (int i = tid; i < 4096; i += 256) stw[i] = g_tabA[i];
    __syncthreads();

    int k1  = tid >> 3;
    int k2b = (tid & 7) * 4;

    float re[4], im[4];
    float t0r, t0i, t8r, t8i;
    unpk2(sT[k1 * 256 + 0], t0r, t0i);
    unpk2(sT[k1 * 256 + 128], t8r, t8i);
#pragma unroll
    for (int j = 0; j < 4; j++) {
        float sg = ((k2b + j) & 1) ? -1.f : 1.f;
        re[j] = t0r + sg * t8r;
        im[j] = t0i + sg * t8i;
    }

    for (int y = 1; y < 128; y++) {
        float ar, ai, br, bi;
        unpk2(sT[k1 * 256 + y], ar, ai);
        unpk2(sT[k1 * 256 + 256 - y], br, bi);
        float Pr = ar + br, Pi = ai + bi;
        float Qr = ar - br, Qi = ai - bi;
        float nQr = -Qr;
        const u64* tw = stw + y * 32 + k2b;
#pragma unroll
        for (int j = 0; j < 4; j++) {
            float c, s; unpk2(tw[j], c, s);
            re[j] = fmaf(Pr, c, fmaf(Qi, s, re[j]));
            im[j] = fmaf(Pi, c, fmaf(nQr, s, im[j]));
        }
    }

#pragma unroll
    for (int j = 0; j < 4; j++)
        g_modes[(size_t)img * 1024 + k1 * 32 + k2b + j] = pk2(re[j], im[j]);
}

// ---------------------------------------------------------------------------
// Per-mode MLP: (re,im) -> 64 relu -> 32 relu -> 1 softplus
// grid 2048 x 256 threads, one mode per thread (pred modes only)
__global__ void __launch_bounds__(256) k_mlp(const float* __restrict__ W1,
                                             const float* __restrict__ b1,
                                             const float* __restrict__ W2,
                                             const float* __restrict__ b2,
                                             const float* __restrict__ W3,
                                             const float* __restrict__ b3,
                                             float* __restrict__ out) {
    __shared__ float sW1[128], sb1[64], sW2[2048], sb2[32], sW3[32], sb3v[1];
    int tid = threadIdx.x;
    if (tid < 128) sW1[tid] = W1[tid];
    if (tid < 64)  sb1[tid] = b1[tid];
    for (int i = tid; i < 2048; i += 256) sW2[i] = W2[i];
    if (tid < 32) { sb2[tid] = b2[tid]; sW3[tid] = W3[tid]; }
    if (tid == 0) sb3v[0] = b3[0];
    __syncthreads();

    int m = blockIdx.x * 256 + tid;
    float re, im; unpk2(g_modes[m], re, im);

    float h1[64];
#pragma unroll
    for (int j = 0; j < 64; j++) {
        float v = fmaf(re, sW1[j], fmaf(im, sW1[64 + j], sb1[j]));
        h1[j] = fmaxf(v, 0.f);
    }

    float acc3 = sb3v[0];
    for (int o = 0; o < 32; o++) {
        float a = sb2[o];
#pragma unroll
        for (int j = 0; j < 64; j++) a = fmaf(h1[j], sW2[j * 32 + o], a);
        a = fmaxf(a, 0.f);
        acc3 = fmaf(a, sW3[o], acc3);
    }

    float sp = (acc3 > 0.f) ? (acc3 + log1pf(expf(-acc3))) : log1pf(expf(acc3));
    out[OFF_MU + m] = sp;
}

// ---------------------------------------------------------------------------
__global__ void k_energy(float* __restrict__ out) {
    int img = blockIdx.x, tid = threadIdx.x;
    float s = 0.f;
    for (int i = tid; i < 1024; i += 256) {
        float r, ii; unpk2(g_modes[(size_t)img * 1024 + i], r, ii);
        float e = fmaf(r, r, ii * ii);
        out[OFF_EN + img * 1024 + i] = e;
        s += e;
    }
    __shared__ float red[256];
    red[tid] = s; __syncthreads();
    for (int o = 128; o > 0; o >>= 1) {
        if (tid < o) red[tid] += red[tid + o];
        __syncthreads();
    }
    if (tid == 0) g_tote[img] = red[0];
}

__global__ void k_post(float* __restrict__ out) {
    int img = blockIdx.x, tid = threadIdx.x;
    float inv = 1.0f / (g_tote[img] + 1e-8f);
    for (int i = tid; i < 1024; i += 256) {
        int idx = img * 1024 + i;
        float e = out[OFF_EN + idx];
        float fr = e * inv;
        out[OFF_FR + idx] = fr;
        out[OFF_WI + idx] = fr * out[OFF_MU + idx];
        float pr, pi, gr, gi;
        unpk2(g_modes[(size_t)img * 1024 + i], pr, pi);
        unpk2(g_modes[(size_t)(NIMG + img) * 1024 + i], gr, gi);
        float dr = pr - gr, di = pi - gi;
        out[OFF_ER + idx] = fmaf(dr, dr, di * di);
    }
}

__global__ void k_spectra(float* __restrict__ out) {
    int m = blockIdx.x * 256 + threadIdx.x;   // 0..1023
    const float* mu = out + OFF_MU;
    const float* en = out + OFF_EN;
    const float* er = out + OFF_ER;
    float su = 0.f, sen = 0.f, ser = 0.f;
    for (int i = 0; i < NIMG; i++) {
        su  += mu[i * 1024 + m];
        sen += en[i * 1024 + m];
        ser += er[i * 1024 + m];
    }
    float ubar = su * (1.0f / NIMG);
    float ebar = ser * (1.0f / NIMG);
    out[OFF_US + m] = ubar;
    out[OFF_ES + m] = sen * (1.0f / NIMG);
    float num = 0.f, d1 = 0.f, d2 = 0.f;
    for (int i = 0; i < NIMG; i++) {
        float du = mu[i * 1024 + m] - ubar;
        float de = er[i * 1024 + m] - ebar;
        num = fmaf(du, de, num);
        d1  = fmaf(du, du, d1);
        d2  = fmaf(de, de, d2);
    }
    out[OFF_CAL + m] = num / (sqrtf(d1 * d2) + 1e-8f);
}

// ---------------------------------------------------------------------------
extern "C" void kernel_launch(void* const* d_in, const int* in_sizes, int n_in,
                              void* d_out, int out_size) {
    const float* pred = (const float*)d_in[0];
    // d_in[1] (uncertainty) is unused by the reference
    const float* gt = (const float*)d_in[2];
    const float* W1 = (const float*)d_in[3];
    const float* b1 = (const float*)d_in[4];
    const float* W2 = (const float*)d_in[5];
    const float* b2 = (const float*)d_in[6];
    const float* W3 = (const float*)d_in[7];
    const float* b3 = (const float*)d_in[8];
    float* out = (float*)d_out;

    const int smemA = 256 * 128 * 4 + 128 * 32 * 8;   // 163840
    const int smemB = (8192 + 4096) * 8;               // 98304
    cudaFuncSetAttribute(k_dft_x, cudaFuncAttributeMaxDynamicSharedMemorySize, smemA);
    cudaFuncSetAttribute(k_dft_y, cudaFuncAttributeMaxDynamicSharedMemorySize, smemB);

    k_init<<<1, 256>>>();
    k_dft_x<<<2048, 256, smemA>>>(pred, gt);
    k_dft_y<<<1024, 256, smemB>>>();
    k_mlp<<<2048, 256>>>(W1, b1, W2, b2, W3, b3, out);
    k_energy<<<NIMG, 256>>>(out);
    k_post<<<NIMG, 256>>>(out);
    k_spectra<<<4, 256>>>(out);
}

// round 4
// speedup vs baseline: 2.4745x; 2.4745x over previous
#include <cuda_runtime.h>
#include <math.h>

// ---------------------------------------------------------------------------
// ModalUncertaintyEstimator — B=64, C=8, H=256, M=32
// outputs (f32, concatenated):
//   [0]       modal_energies        512*1024
//   [524288]  modal_uncertainties   512*1024
//   [1048576] energy_fractions      512*1024
//   [1572864] weighted_importance   512*1024
//   [2097152] uncertainty_spectrum  1024
//   [2098176] energy_spectrum       1024
//   [2099200] modal_errors          512*1024
//   [2623488] calibration_scores    1024
// ---------------------------------------------------------------------------

#define NIMG 512          // B*C
#define SZ   (NIMG * 1024)

#define OFF_EN  0
#define OFF_MU  (SZ)
#define OFF_FR  (2 * SZ)
#define OFF_WI  (3 * SZ)
#define OFF_US  (4 * SZ)
#define OFF_ES  (4 * SZ + 1024)
#define OFF_ER  (4 * SZ + 2048)
#define OFF_CAL (5 * SZ + 2048)

typedef unsigned long long u64;

__device__ __forceinline__ u64 pk2(float x, float y) {
    u64 r; asm("mov.b64 %0,{%1,%2};" : "=l"(r) : "f"(x), "f"(y)); return r;
}
__device__ __forceinline__ void unpk2(u64 v, float& x, float& y) {
    asm("mov.b64 {%0,%1},%2;" : "=f"(x), "=f"(y) : "l"(v));
}
__device__ __forceinline__ u64 ffma2(u64 a, u64 b, u64 c) {
    u64 d; asm("fma.rn.f32x2 %0,%1,%2,%3;" : "=l"(d) : "l"(a), "l"(b), "l"(c)); return d;
}
__device__ __forceinline__ u64 add2(u64 a, u64 b) {
    u64 d; asm("add.rn.f32x2 %0,%1,%2;" : "=l"(d) : "l"(a), "l"(b)); return d;
}
__device__ __forceinline__ u64 relu2(u64 v) {
    float a, b; unpk2(v, a, b);
    return pk2(fmaxf(a, 0.f), fmaxf(b, 0.f));
}
__device__ __forceinline__ float softplus_f(float x) {
    return (x > 0.f) ? x + log1pf(expf(-x)) : log1pf(expf(x));
}

// ---------------------------------------------------------------------------
// compile-time twiddle tables: (cos,sin)(2*pi*(x*k)/256) for x<64, k<32
// quadrant-reduced Taylor (double) so |t| <= pi/2 -> full precision
// ---------------------------------------------------------------------------
struct Tab { float c[64][32]; float s[64][32]; };

constexpr double TAU_ = 6.283185307179586476925286766559;
constexpr double tsin_(double t) {
    double t2 = t * t, term = t, r = t;
    for (int i = 1; i <= 12; i++) { term *= -t2 / (double)((2 * i) * (2 * i + 1)); r += term; }
    return r;
}
constexpr double tcos_(double t) {
    double t2 = t * t, term = 1.0, r = 1.0;
    for (int i = 1; i <= 12; i++) { term *= -t2 / (double)((2 * i - 1) * (2 * i)); r += term; }
    return r;
}
constexpr Tab mk_tab() {
    Tab t{};
    for (int x = 0; x < 64; x++)
        for (int k = 0; k < 32; k++) {
            int n = (x * k) & 255;
            int q = n >> 6, rr = n & 63;
            double th = (TAU_ / 256.0) * (double)rr;
            double c = tcos_(th), s = tsin_(th);
            double cc = c, ss = s;
            if (q == 1) { cc = -s; ss = c; }
            else if (q == 2) { cc = -c; ss = -s; }
            else if (q == 3) { cc = s; ss = -c; }
            t.c[x][k] = (float)cc; t.s[x][k] = (float)ss;
        }
    return t;
}
__device__ constexpr Tab TW = mk_tab();

// scratch (device globals: allocation-free)
__device__ u64   g_modes[1024 * 1024];    // [img][k1*32+k2]; imgs 0..511 pred, 512..1023 gt
__device__ float g_tote[NIMG];

// ---------------------------------------------------------------------------
// Fused 2-D partial DFT: one block per image (1024 blocks).
// Stage A (256 thr, thread = column y): T1[y][k1], double-folded over x.
// Stage B (128 thr, thread = (k1, 8 k2)): modes[k1][k2], double-folded over y.
// T1 lives in dynamic smem [256][33] u64 (padded rows, 67584 B).
// All twiddles are compile-time immediates (FFMA imm-form, rt_SMSP=1).
// ---------------------------------------------------------------------------
__global__ void __launch_bounds__(256) k_dft(const float* __restrict__ pred,
                                             const float* __restrict__ gt) {
    extern __shared__ u64 T1s[];   // [y][k] stride 33
    int img = blockIdx.x;
    const float* src = (img < NIMG) ? (pred + (size_t)img * 65536)
                                    : (gt + (size_t)(img - NIMG) * 65536);
    int tid = threadIdx.x;

    // ---------------- stage A ----------------
    {
        const float* col = src + tid;                 // f[x] = col[x*256]
        float f0 = col[0], f64v = col[64 * 256], f128 = col[128 * 256], f192 = col[192 * 256];
        float e64 = f64v + f192, o64 = f64v - f192;

        float re[32], im[32];                          // im holds +sum(o*sin); negate at store
#pragma unroll
        for (int k = 0; k < 32; k++) {
            float r = f0 + ((k & 1) ? -f128 : f128);
            int q = k & 3;
            if (q == 0) r += e64; else if (q == 2) r -= e64;
            re[k] = r;
            im[k] = (q == 1) ? o64 : ((q == 3) ? -o64 : 0.f);
        }

#pragma unroll
        for (int x = 1; x < 64; x++) {
            float fa = col[x * 256];
            float fb = col[(128 - x) * 256];
            float fc = col[(128 + x) * 256];
            float fd = col[(256 - x) * 256];
            float e1 = fa + fd, o1 = fa - fd;          // pair (x, 256-x)
            float e2 = fb + fc, o2 = fb - fc;          // pair (128-x, 128+x)
            float ep = e1 + e2, em = e1 - e2;
            float sp = o1 + o2, sm = o1 - o2;
#pragma unroll
            for (int k = 0; k < 32; k++) {
                float c = TW.c[x][k], s = TW.s[x][k];
                if (k & 1) { re[k] = fmaf(em, c, re[k]); im[k] = fmaf(sp, s, im[k]); }
                else       { re[k] = fmaf(ep, c, re[k]); im[k] = fmaf(sm, s, im[k]); }
            }
        }
#pragma unroll
        for (int k = 0; k < 32; k++) T1s[tid * 33 + k] = pk2(re[k], -im[k]);
    }
    __syncthreads();

    // ---------------- stage B ----------------
    if (tid < 128) {
        int k1 = tid >> 2, k2b = (tid & 3) * 8;
        float a0r, a0i, a128r, a128i, t64r, t64i, t192r, t192i;
        unpk2(T1s[0 * 33 + k1], a0r, a0i);
        unpk2(T1s[128 * 33 + k1], a128r, a128i);
        unpk2(T1s[64 * 33 + k1], t64r, t64i);
        unpk2(T1s[192 * 33 + k1], t192r, t192i);
        float P64r = t64r + t192r, P64i = t64i + t192i;
        float Q64r = t64r - t192r, Q64i = t64i - t192i;

        float re[8], im[8];
#pragma unroll
        for (int j = 0; j < 8; j++) {
            int k2 = k2b + j;
            float r = a0r + ((k2 & 1) ? -a128r : a128r);
            float m = a0i + ((k2 & 1) ? -a128i : a128i);
            int q = k2 & 3;
            if (q == 0) { r += P64r; m += P64i; }
            else if (q == 1) { r += Q64i; m -= Q64r; }
            else if (q == 2) { r -= P64r; m -= P64i; }
            else { r -= Q64i; m += Q64r; }
            re[j] = r; im[j] = m;
        }

        u64 NEG1 = pk2(-1.f, -1.f);
#pragma unroll
        for (int y = 1; y < 64; y++) {
            u64 ta = T1s[y * 33 + k1];
            u64 tb = T1s[(128 - y) * 33 + k1];
            u64 tc = T1s[(128 + y) * 33 + k1];
            u64 td = T1s[(256 - y) * 33 + k1];
            u64 P1 = add2(ta, td), Q1 = ffma2(td, NEG1, ta);
            u64 P2 = add2(tb, tc), Q2 = ffma2(tc, NEG1, tb);
            u64 Pp = add2(P1, P2), Pm = ffma2(P2, NEG1, P1);
            u64 Qp = add2(Q1, Q2), Qm = ffma2(Q2, NEG1, Q1);
            float Ppr, Ppi, Pmr, Pmi, Qpr, Qpi, Qmr, Qmi;
            unpk2(Pp, Ppr, Ppi); unpk2(Pm, Pmr, Pmi);
            unpk2(Qp, Qpr, Qpi); unpk2(Qm, Qmr, Qmi);
#pragma unroll
            for (int j = 0; j < 8; j++) {
                int k2 = k2b + j;
                float c = TW.c[y][k2], s = TW.s[y][k2];
                if (k2 & 1) {
                    re[j] = fmaf(Pmr, c, fmaf(Qpi, s, re[j]));
                    im[j] = fmaf(Pmi, c, fmaf(Qpr, -s, im[j]));
                } else {
                    re[j] = fmaf(Ppr, c, fmaf(Qmi, s, re[j]));
                    im[j] = fmaf(Ppi, c, fmaf(Qmr, -s, im[j]));
                }
            }
        }
#pragma unroll
        for (int j = 0; j < 8; j++)
            g_modes[(size_t)img * 1024 + k1 * 32 + k2b + j] = pk2(re[j], im[j]);
    }
}

// ---------------------------------------------------------------------------
// Per-mode MLP, 2 modes/thread, hidden dim packed into f32x2 lanes.
// grid 1024 x 256 (pred modes only).
// ---------------------------------------------------------------------------
__global__ void __launch_bounds__(256) k_mlp(const float* __restrict__ W1,
                                             const float* __restrict__ b1,
                                             const float* __restrict__ W2,
                                             const float* __restrict__ b2,
                                             const float* __restrict__ W3,
                                             const float* __restrict__ b3,
                                             float* __restrict__ out) {
    __shared__ __align__(16) float sW1[128];     // raw [2][64]
    __shared__ __align__(16) float sb1[64];
    __shared__ __align__(16) u64 sW2p[1024];     // [o][j2] = (W2[2j2][o], W2[2j2+1][o])
    __shared__ float sb2[32], sW3[32], sb3v;
    int tid = threadIdx.x;
    if (tid < 128) sW1[tid] = W1[tid];
    if (tid < 64)  sb1[tid] = b1[tid];
    for (int i = tid; i < 1024; i += 256) {
        int o = i >> 5, j2 = i & 31;
        sW2p[i] = pk2(W2[j2 * 64 + o], W2[j2 * 64 + 32 + o]);
    }
    if (tid < 32) { sb2[tid] = b2[tid]; sW3[tid] = W3[tid]; }
    if (tid == 0) sb3v = b3[0];
    __syncthreads();

    int base = (blockIdx.x * 256 + tid) * 2;
    float re0, im0, re1, im1;
    unpk2(g_modes[base], re0, im0);
    unpk2(g_modes[base + 1], re1, im1);
    u64 r0 = pk2(re0, re0), i0 = pk2(im0, im0);
    u64 r1 = pk2(re1, re1), i1 = pk2(im1, im1);

    // layer 1: 64 hidden as 32 lane-pairs, per mode
    u64 h0[32], h1v[32];
    const u64* w1r = (const u64*)sW1;
    const u64* w1i = (const u64*)(sW1 + 64);
    const u64* b1p = (const u64*)sb1;
#pragma unroll
    for (int j2 = 0; j2 < 32; j2++) {
        u64 b = b1p[j2], wr = w1r[j2], wi = w1i[j2];
        h0[j2]  = relu2(ffma2(r0, wr, ffma2(i0, wi, b)));
        h1v[j2] = relu2(ffma2(r1, wr, ffma2(i1, wi, b)));
    }

    // layers 2+3: 4 independent f32x2 chains per output
    float acc3_0 = sb3v, acc3_1 = sb3v;
#pragma unroll 4
    for (int o = 0; o < 32; o++) {
        const ulonglong2* wp = (const ulonglong2*)&sW2p[o * 32];
        u64 aA0 = 0ull, aB0 = 0ull, aA1 = 0ull, aB1 = 0ull;
#pragma unroll
        for (int q = 0; q < 16; q++) {
            ulonglong2 w = wp[q];
            aA0 = ffma2(h0[2 * q],      w.x, aA0);
            aB0 = ffma2(h0[2 * q + 1],  w.y, aB0);
            aA1 = ffma2(h1v[2 * q],     w.x, aA1);
            aB1 = ffma2(h1v[2 * q + 1], w.y, aB1);
        }
        float xa, ya, xb, yb;
        unpk2(aA0, xa, ya); unpk2(aB0, xb, yb);
        float l2_0 = sb2[o] + ((xa + ya) + (xb + yb));
        unpk2(aA1, xa, ya); unpk2(aB1, xb, yb);
        float l2_1 = sb2[o] + ((xa + ya) + (xb + yb));
        float w3 = sW3[o];
        acc3_0 = fmaf(fmaxf(l2_0, 0.f), w3, acc3_0);
        acc3_1 = fmaf(fmaxf(l2_1, 0.f), w3, acc3_1);
    }

    out[OFF_MU + base]     = softplus_f(acc3_0);
    out[OFF_MU + base + 1] = softplus_f(acc3_1);
}

// ---------------------------------------------------------------------------
// Fused per-image pass: energies + errors + total-energy reduce + fractions
// + weighted importance. One block per image (512 blocks).
// ---------------------------------------------------------------------------
__global__ void __launch_bounds__(256) k_energy(float* __restrict__ out) {
    int img = blockIdx.x, tid = threadIdx.x;
    __shared__ float sE[1024];
    __shared__ float red[256];

    float s = 0.f;
#pragma unroll
    for (int u = 0; u < 4; u++) {
        int i = tid + u * 256;
        float pr, pi, gr, gi;
        unpk2(g_modes[(size_t)img * 1024 + i], pr, pi);
        unpk2(g_modes[(size_t)(NIMG + img) * 1024 + i], gr, gi);
        float e = fmaf(pr, pr, pi * pi);
        sE[i] = e;
        out[OFF_EN + img * 1024 + i] = e;
        float dr = pr - gr, di = pi - gi;
        out[OFF_ER + img * 1024 + i] = fmaf(dr, dr, di * di);
        s += e;
    }
    red[tid] = s; __syncthreads();
    for (int o = 128; o > 0; o >>= 1) {
        if (tid < o) red[tid] += red[tid + o];
        __syncthreads();
    }
    float inv = 1.0f / (red[0] + 1e-8f);
#pragma unroll
    for (int u = 0; u < 4; u++) {
        int i = tid + u * 256;
        int idx = img * 1024 + i;
        float fr = sE[i] * inv;
        out[OFF_FR + idx] = fr;
        out[OFF_WI + idx] = fr * out[OFF_MU + idx];
    }
}

// ---------------------------------------------------------------------------
// one block per mode: two-pass (centered) Pearson + spectra means
// ---------------------------------------------------------------------------
__device__ __forceinline__ float blocksum(float v, float* red, int tid) {
    __syncthreads();
    red[tid] = v; __syncthreads();
    for (int o = 128; o > 0; o >>= 1) {
        if (tid < o) red[tid] += red[tid + o];
        __syncthreads();
    }
    return red[0];
}

__global__ void __launch_bounds__(256) k_spectra(float* __restrict__ out) {
    int m = blockIdx.x;       // 0..1023
    int tid = threadIdx.x;
    __shared__ float smu[512], sen[512], ser[512];
    __shared__ float red[256];
    for (int i = tid; i < 512; i += 256) {
        smu[i] = out[OFF_MU + i * 1024 + m];
        sen[i] = out[OFF_EN + i * 1024 + m];
        ser[i] = out[OFF_ER + i * 1024 + m];
    }
    __syncthreads();
    float su = smu[tid] + smu[tid + 256];
    float se = sen[tid] + sen[tid + 256];
    float sr = ser[tid] + ser[tid + 256];
    float tu = blocksum(su, red, tid);
    float te = blocksum(se, red, tid);
    float tr = blocksum(sr, red, tid);
    float ubar = tu * (1.0f / NIMG);
    float ebar = tr * (1.0f / NIMG);

    float du0 = smu[tid] - ubar, du1 = smu[tid + 256] - ubar;
    float de0 = ser[tid] - ebar, de1 = ser[tid + 256] - ebar;
    float num = fmaf(du0, de0, du1 * de1);
    float d1  = fmaf(du0, du0, du1 * du1);
    float d2  = fmaf(de0, de0, de1 * de1);
    float tn = blocksum(num, red, tid);
    float t1 = blocksum(d1, red, tid);
    float t2 = blocksum(d2, red, tid);

    if (tid == 0) {
        out[OFF_US + m]  = ubar;
        out[OFF_ES + m]  = te * (1.0f / NIMG);
        out[OFF_CAL + m] = tn / (sqrtf(t1 * t2) + 1e-8f);
    }
}

// ---------------------------------------------------------------------------
extern "C" void kernel_launch(void* const* d_in, const int* in_sizes, int n_in,
                              void* d_out, int out_size) {
    const float* pred = (const float*)d_in[0];
    // d_in[1] (uncertainty) is unused by the reference
    const float* gt = (const float*)d_in[2];
    const float* W1 = (const float*)d_in[3];
    const float* b1 = (const float*)d_in[4];
    const float* W2 = (const float*)d_in[5];
    const float* b2 = (const float*)d_in[6];
    const float* W3 = (const float*)d_in[7];
    const float* b3 = (const float*)d_in[8];
    float* out = (float*)d_out;

    const int smemD = 256 * 33 * 8;   // 67584
    cudaFuncSetAttribute(k_dft, cudaFuncAttributeMaxDynamicSharedMemorySize, smemD);

    k_dft<<<1024, 256, smemD>>>(pred, gt);
    k_mlp<<<1024, 256>>>(W1, b1, W2, b2, W3, b3, out);
    k_energy<<<NIMG, 256>>>(out);
    k_spectra<<<1024, 256>>>(out);
}

// round 5
// speedup vs baseline: 3.1313x; 1.2654x over previous
#include <cuda_runtime.h>
#include <math.h>

// ---------------------------------------------------------------------------
// ModalUncertaintyEstimator — B=64, C=8, H=256, M=32
// ---------------------------------------------------------------------------

#define NIMG 512          // B*C
#define SZ   (NIMG * 1024)

#define OFF_EN  0
#define OFF_MU  (SZ)
#define OFF_FR  (2 * SZ)
#define OFF_WI  (3 * SZ)
#define OFF_US  (4 * SZ)
#define OFF_ES  (4 * SZ + 1024)
#define OFF_ER  (4 * SZ + 2048)
#define OFF_CAL (5 * SZ + 2048)

typedef unsigned long long u64;

__device__ __forceinline__ u64 pk2(float x, float y) {
    u64 r; asm("mov.b64 %0,{%1,%2};" : "=l"(r) : "f"(x), "f"(y)); return r;
}
__device__ __forceinline__ void unpk2(u64 v, float& x, float& y) {
    asm("mov.b64 {%0,%1},%2;" : "=f"(x), "=f"(y) : "l"(v));
}
__device__ __forceinline__ u64 ffma2(u64 a, u64 b, u64 c) {
    u64 d; asm("fma.rn.f32x2 %0,%1,%2,%3;" : "=l"(d) : "l"(a), "l"(b), "l"(c)); return d;
}
__device__ __forceinline__ u64 add2(u64 a, u64 b) {
    u64 d; asm("add.rn.f32x2 %0,%1,%2;" : "=l"(d) : "l"(a), "l"(b)); return d;
}
__device__ __forceinline__ u64 relu2(u64 v) {
    float a, b; unpk2(v, a, b);
    return pk2(fmaxf(a, 0.f), fmaxf(b, 0.f));
}
__device__ __forceinline__ float softplus_f(float x) {
    return (x > 0.f) ? x + log1pf(expf(-x)) : log1pf(expf(x));
}

// ---------------------------------------------------------------------------
// compile-time twiddle tables: (cos,sin)(2*pi*(x*k)/256) for x<64, k<32
// ---------------------------------------------------------------------------
struct Tab { float c[64][32]; float s[64][32]; };

constexpr double TAU_ = 6.283185307179586476925286766559;
constexpr double tsin_(double t) {
    double t2 = t * t, term = t, r = t;
    for (int i = 1; i <= 12; i++) { term *= -t2 / (double)((2 * i) * (2 * i + 1)); r += term; }
    return r;
}
constexpr double tcos_(double t) {
    double t2 = t * t, term = 1.0, r = 1.0;
    for (int i = 1; i <= 12; i++) { term *= -t2 / (double)((2 * i - 1) * (2 * i)); r += term; }
    return r;
}
constexpr Tab mk_tab() {
    Tab t{};
    for (int x = 0; x < 64; x++)
        for (int k = 0; k < 32; k++) {
            int n = (x * k) & 255;
            int q = n >> 6, rr = n & 63;
            double th = (TAU_ / 256.0) * (double)rr;
            double c = tcos_(th), s = tsin_(th);
            double cc = c, ss = s;
            if (q == 1) { cc = -s; ss = c; }
            else if (q == 2) { cc = -c; ss = -s; }
            else if (q == 3) { cc = s; ss = -c; }
            t.c[x][k] = (float)cc; t.s[x][k] = (float)ss;
        }
    return t;
}
__device__ constexpr Tab TW = mk_tab();

// scratch (device globals: allocation-free)
__device__ u64 g_modes[1024 * 1024];    // [img][k1*32+k2]; imgs 0..511 pred, 512..1023 gt

// ---------------------------------------------------------------------------
// Fused 2-D partial DFT: one block per image (1024 blocks), 2 blocks/SM.
// Stage A (256 thr, thread = column y): T1[y][k1], double-folded over x.
// Stage B (256 thr, thread = (k1, 4 k2)): modes[k1][k2], double-folded over y.
// T1 in dynamic smem [256][33] u64 (padded rows, 67584 B; 2x fits 228KB).
// Twiddles are compile-time immediates (FFMA imm-form, rt_SMSP=1).
// ---------------------------------------------------------------------------
__global__ void __launch_bounds__(256, 2) k_dft(const float* __restrict__ pred,
                                                const float* __restrict__ gt) {
    extern __shared__ u64 T1s[];   // [y][k] stride 33
    int img = blockIdx.x;
    const float* src = (img < NIMG) ? (pred + (size_t)img * 65536)
                                    : (gt + (size_t)(img - NIMG) * 65536);
    int tid = threadIdx.x;

    // ---------------- stage A ----------------
    {
        const float* col = src + tid;                 // f[x] = col[x*256]
        float f0 = col[0], f64v = col[64 * 256], f128 = col[128 * 256], f192 = col[192 * 256];
        float e64 = f64v + f192, o64 = f64v - f192;

        float re[32], im[32];                          // im holds +sum(o*sin); negate at store
#pragma unroll
        for (int k = 0; k < 32; k++) {
            float r = f0 + ((k & 1) ? -f128 : f128);
            int q = k & 3;
            if (q == 0) r += e64; else if (q == 2) r -= e64;
            re[k] = r;
            im[k] = (q == 1) ? o64 : ((q == 3) ? -o64 : 0.f);
        }

#pragma unroll
        for (int x = 1; x < 64; x++) {
            float fa = col[x * 256];
            float fb = col[(128 - x) * 256];
            float fc = col[(128 + x) * 256];
            float fd = col[(256 - x) * 256];
            float e1 = fa + fd, o1 = fa - fd;          // pair (x, 256-x)
            float e2 = fb + fc, o2 = fb - fc;          // pair (128-x, 128+x)
            float ep = e1 + e2, em = e1 - e2;
            float sp = o1 + o2, sm = o1 - o2;
#pragma unroll
            for (int k = 0; k < 32; k++) {
                float c = TW.c[x][k], s = TW.s[x][k];
                if (k & 1) { re[k] = fmaf(em, c, re[k]); im[k] = fmaf(sp, s, im[k]); }
                else       { re[k] = fmaf(ep, c, re[k]); im[k] = fmaf(sm, s, im[k]); }
            }
        }
#pragma unroll
        for (int k = 0; k < 32; k++) T1s[tid * 33 + k] = pk2(re[k], -im[k]);
    }
    __syncthreads();

    // ---------------- stage B (all 256 threads, 4 k2 each) ----------------
    {
        int k1 = tid >> 3, k2b = (tid & 7) * 4;
        float a0r, a0i, a128r, a128i, t64r, t64i, t192r, t192i;
        unpk2(T1s[0 * 33 + k1], a0r, a0i);
        unpk2(T1s[128 * 33 + k1], a128r, a128i);
        unpk2(T1s[64 * 33 + k1], t64r, t64i);
        unpk2(T1s[192 * 33 + k1], t192r, t192i);
        float P64r = t64r + t192r, P64i = t64i + t192i;
        float Q64r = t64r - t192r, Q64i = t64i - t192i;

        float re[4], im[4];
#pragma unroll
        for (int j = 0; j < 4; j++) {
            int k2 = k2b + j;
            float r = a0r + ((k2 & 1) ? -a128r : a128r);
            float m = a0i + ((k2 & 1) ? -a128i : a128i);
            int q = k2 & 3;
            if (q == 0) { r += P64r; m += P64i; }
            else if (q == 1) { r += Q64i; m -= Q64r; }
            else if (q == 2) { r -= P64r; m -= P64i; }
            else { r -= Q64i; m += Q64r; }
            re[j] = r; im[j] = m;
        }

        u64 NEG1 = pk2(-1.f, -1.f);
#pragma unroll
        for (int y = 1; y < 64; y++) {
            u64 ta = T1s[y * 33 + k1];
            u64 tb = T1s[(128 - y) * 33 + k1];
            u64 tc = T1s[(128 + y) * 33 + k1];
            u64 td = T1s[(256 - y) * 33 + k1];
            u64 P1 = add2(ta, td), Q1 = ffma2(td, NEG1, ta);
            u64 P2 = add2(tb, tc), Q2 = ffma2(tc, NEG1, tb);
            u64 Pp = add2(P1, P2), Pm = ffma2(P2, NEG1, P1);
            u64 Qp = add2(Q1, Q2), Qm = ffma2(Q2, NEG1, Q1);
            float Ppr, Ppi, Pmr, Pmi, Qpr, Qpi, Qmr, Qmi;
            unpk2(Pp, Ppr, Ppi); unpk2(Pm, Pmr, Pmi);
            unpk2(Qp, Qpr, Qpi); unpk2(Qm, Qmr, Qmi);
#pragma unroll
            for (int j = 0; j < 4; j++) {
                int k2 = k2b + j;
                float c = TW.c[y][k2], s = TW.s[y][k2];
                if (k2 & 1) {
                    re[j] = fmaf(Pmr, c, fmaf(Qpi, s, re[j]));
                    im[j] = fmaf(Pmi, c, fmaf(Qpr, -s, im[j]));
                } else {
                    re[j] = fmaf(Ppr, c, fmaf(Qmi, s, re[j]));
                    im[j] = fmaf(Ppi, c, fmaf(Qmr, -s, im[j]));
                }
            }
        }
#pragma unroll
        for (int j = 0; j < 4; j++)
            g_modes[(size_t)img * 1024 + k1 * 32 + k2b + j] = pk2(re[j], im[j]);
    }
}

// ---------------------------------------------------------------------------
// Per-mode MLP, 2 modes/thread, hidden dim packed into f32x2 lanes.
// ---------------------------------------------------------------------------
__global__ void __launch_bounds__(256) k_mlp(const float* __restrict__ W1,
                                             const float* __restrict__ b1,
                                             const float* __restrict__ W2,
                                             const float* __restrict__ b2,
                                             const float* __restrict__ W3,
                                             const float* __restrict__ b3,
                                             float* __restrict__ out) {
    __shared__ __align__(16) float sW1[128];     // raw [2][64]
    __shared__ __align__(16) float sb1[64];
    __shared__ __align__(16) u64 sW2p[1024];     // [o][j2] = (W2[2j2][o], W2[2j2+1][o])
    __shared__ float sb2[32], sW3[32], sb3v;
    int tid = threadIdx.x;
    if (tid < 128) sW1[tid] = W1[tid];
    if (tid < 64)  sb1[tid] = b1[tid];
    for (int i = tid; i < 1024; i += 256) {
        int o = i >> 5, j2 = i & 31;
        sW2p[i] = pk2(W2[j2 * 64 + o], W2[j2 * 64 + 32 + o]);
    }
    if (tid < 32) { sb2[tid] = b2[tid]; sW3[tid] = W3[tid]; }
    if (tid == 0) sb3v = b3[0];
    __syncthreads();

    int base = (blockIdx.x * 256 + tid) * 2;
    float re0, im0, re1, im1;
    unpk2(g_modes[base], re0, im0);
    unpk2(g_modes[base + 1], re1, im1);
    u64 r0 = pk2(re0, re0), i0 = pk2(im0, im0);
    u64 r1 = pk2(re1, re1), i1 = pk2(im1, im1);

    u64 h0[32], h1v[32];
    const u64* w1r = (const u64*)sW1;
    const u64* w1i = (const u64*)(sW1 + 64);
    const u64* b1p = (const u64*)sb1;
#pragma unroll
    for (int j2 = 0; j2 < 32; j2++) {
        u64 b = b1p[j2], wr = w1r[j2], wi = w1i[j2];
        h0[j2]  = relu2(ffma2(r0, wr, ffma2(i0, wi, b)));
        h1v[j2] = relu2(ffma2(r1, wr, ffma2(i1, wi, b)));
    }

    float acc3_0 = sb3v, acc3_1 = sb3v;
#pragma unroll 4
    for (int o = 0; o < 32; o++) {
        const ulonglong2* wp = (const ulonglong2*)&sW2p[o * 32];
        u64 aA0 = 0ull, aB0 = 0ull, aA1 = 0ull, aB1 = 0ull;
#pragma unroll
        for (int q = 0; q < 16; q++) {
            ulonglong2 w = wp[q];
            aA0 = ffma2(h0[2 * q],      w.x, aA0);
            aB0 = ffma2(h0[2 * q + 1],  w.y, aB0);
            aA1 = ffma2(h1v[2 * q],     w.x, aA1);
            aB1 = ffma2(h1v[2 * q + 1], w.y, aB1);
        }
        float xa, ya, xb, yb;
        unpk2(aA0, xa, ya); unpk2(aB0, xb, yb);
        float l2_0 = sb2[o] + ((xa + ya) + (xb + yb));
        unpk2(aA1, xa, ya); unpk2(aB1, xb, yb);
        float l2_1 = sb2[o] + ((xa + ya) + (xb + yb));
        float w3 = sW3[o];
        acc3_0 = fmaf(fmaxf(l2_0, 0.f), w3, acc3_0);
        acc3_1 = fmaf(fmaxf(l2_1, 0.f), w3, acc3_1);
    }

    out[OFF_MU + base]     = softplus_f(acc3_0);
    out[OFF_MU + base + 1] = softplus_f(acc3_1);
}

// ---------------------------------------------------------------------------
// Fused per-image pass: energies + errors + total-energy reduce + fractions
// + weighted importance. One block per image (512 blocks).
// ---------------------------------------------------------------------------
__global__ void __launch_bounds__(256) k_energy(float* __restrict__ out) {
    int img = blockIdx.x, tid = threadIdx.x;
    __shared__ float sE[1024];
    __shared__ float red[256];

    float s = 0.f;
#pragma unroll
    for (int u = 0; u < 4; u++) {
        int i = tid + u * 256;
        float pr, pi, gr, gi;
        unpk2(g_modes[(size_t)img * 1024 + i], pr, pi);
        unpk2(g_modes[(size_t)(NIMG + img) * 1024 + i], gr, gi);
        float e = fmaf(pr, pr, pi * pi);
        sE[i] = e;
        out[OFF_EN + img * 1024 + i] = e;
        float dr = pr - gr, di = pi - gi;
        out[OFF_ER + img * 1024 + i] = fmaf(dr, dr, di * di);
        s += e;
    }
    red[tid] = s; __syncthreads();
    for (int o = 128; o > 0; o >>= 1) {
        if (tid < o) red[tid] += red[tid + o];
        __syncthreads();
    }
    float inv = 1.0f / (red[0] + 1e-8f);
#pragma unroll
    for (int u = 0; u < 4; u++) {
        int i = tid + u * 256;
        int idx = img * 1024 + i;
        float fr = sE[i] * inv;
        out[OFF_FR + idx] = fr;
        out[OFF_WI + idx] = fr * out[OFF_MU + idx];
    }
}

// ---------------------------------------------------------------------------
// Spectra + Pearson, coalesced: 64 blocks x 256 thr, 16 modes/block.
// thread = (mode lane ml = tid&15, image group rg = tid>>4, stride 16).
// Two passes over L2-hot data (6 MB), exact centered Pearson.
// ---------------------------------------------------------------------------
__device__ __forceinline__ float bsum16(float v, float (*red)[16], int rg, int ml) {
    __syncthreads();
    red[rg][ml] = v;
    __syncthreads();
    if (rg == 0) {
        float t = 0.f;
#pragma unroll
        for (int r = 0; r < 16; r++) t += red[r][ml];
        red[0][ml] = t;
    }
    __syncthreads();
    return red[0][ml];
}

__global__ void __launch_bounds__(256) k_spectra(float* __restrict__ out) {
    __shared__ float red[16][16];
    int tid = threadIdx.x;
    int ml = tid & 15, rg = tid >> 4;
    int m = blockIdx.x * 16 + ml;

    const float* mu = out + OFF_MU;
    const float* en = out + OFF_EN;
    const float* er = out + OFF_ER;

    // pass 1: sums
    float su = 0.f, se = 0.f, sr = 0.f;
    for (int i = rg; i < NIMG; i += 16) {
        su += mu[i * 1024 + m];
        se += en[i * 1024 + m];
        sr += er[i * 1024 + m];
    }
    float tu = bsum16(su, red, rg, ml);
    float te = bsum16(se, red, rg, ml);
    float tr = bsum16(sr, red, rg, ml);
    float ubar = tu * (1.0f / NIMG);
    float ebar = tr * (1.0f / NIMG);

    // pass 2: centered moments
    float num = 0.f, d1 = 0.f, d2 = 0.f;
    for (int i = rg; i < NIMG; i += 16) {
        float du = mu[i * 1024 + m] - ubar;
        float de = er[i * 1024 + m] - ebar;
        num = fmaf(du, de, num);
        d1  = fmaf(du, du, d1);
        d2  = fmaf(de, de, d2);
    }
    float tn = bsum16(num, red, rg, ml);
    float t1 = bsum16(d1, red, rg, ml);
    float t2 = bsum16(d2, red, rg, ml);

    if (rg == 0) {
        out[OFF_US + m]  = ubar;
        out[OFF_ES + m]  = te * (1.0f / NIMG);
        out[OFF_CAL + m] = tn / (sqrtf(t1 * t2) + 1e-8f);
    }
}

// ---------------------------------------------------------------------------
extern "C" void kernel_launch(void* const* d_in, const int* in_sizes, int n_in,
                              void* d_out, int out_size) {
    const float* pred = (const float*)d_in[0];
    // d_in[1] (uncertainty) is unused by the reference
    const float* gt = (const float*)d_in[2];
    const float* W1 = (const float*)d_in[3];
    const float* b1 = (const float*)d_in[4];
    const float* W2 = (const float*)d_in[5];
    const float* b2 = (const float*)d_in[6];
    const float* W3 = (const float*)d_in[7];
    const float* b3 = (const float*)d_in[8];
    float* out = (float*)d_out;

    const int smemD = 256 * 33 * 8;   // 67584
    cudaFuncSetAttribute(k_dft, cudaFuncAttributeMaxDynamicSharedMemorySize, smemD);

    k_dft<<<1024, 256, smemD>>>(pred, gt);
    k_mlp<<<1024, 256>>>(W1, b1, W2, b2, W3, b3, out);
    k_energy<<<NIMG, 256>>>(out);
    k_spectra<<<64, 256>>>(out);
}